// round 15
// baseline (speedup 1.0000x reference)
#include <cuda_runtime.h>
#include <cstdint>

#define NROWS 256
#define DDIM  768
#define KD    128
#define NK    500
#define TK    4

// output layout (float32, reference return order)
#define OC_OFF  0
#define IDX_OFF 786432
#define SC_OFF  787456
#define QP_OFF  788480

#define NEG_INF (-3.402823466e38f)

#define SW_PAD 20                      // W tile row stride (floats): 16B-aligned
#define K1_DSMEM ((8 * 772 + DDIM * SW_PAD) * 4)   // bytes

__device__ float g_q[NROWS * KD];                      // queries
__device__ unsigned long long g_cand[2][NROWS][32];    // per (side,row): 8 tiles x top-4, packed

// ---- packed candidate: sortable float in high 32, ~idx in low 32 ----
__device__ __forceinline__ unsigned long long packcand(float f, int idx) {
    unsigned int b = __float_as_uint(f);
    unsigned int s = (b & 0x80000000u) ? ~b : (b | 0x80000000u);
    return ((unsigned long long)s << 32) | (unsigned int)(~idx);
}
__device__ __forceinline__ float unpackval(unsigned long long c) {
    unsigned int s = (unsigned int)(c >> 32);
    unsigned int b = (s & 0x80000000u) ? (s & 0x7FFFFFFFu) : ~s;
    return __uint_as_float(b);
}
__device__ __forceinline__ int unpackidx(unsigned long long c) {
    return (int)(~(unsigned int)(c & 0xFFFFFFFFu));
}

// sorted desc top-4 list of packed u64
__device__ __forceinline__ void insert4u(unsigned long long* v, unsigned long long x) {
    if (x <= v[3]) return;
    v[3] = x;
    if (v[3] > v[2]) { unsigned long long tt = v[3]; v[3] = v[2]; v[2] = tt; }
    if (v[2] > v[1]) { unsigned long long tt = v[2]; v[2] = v[1]; v[1] = tt; }
    if (v[1] > v[0]) { unsigned long long tt = v[1]; v[1] = v[0]; v[0] = tt; }
}

// ---------------------------------------------------------------------------
// K1: LN + Q = LN(x) @ Wq + bq
// grid (8 coltiles of 16, 32 rowtiles of 8), 256 threads
// W tile prefetched to smem at entry (overlaps LN prologue); GEMM is LDS-only
// ---------------------------------------------------------------------------
__global__ __launch_bounds__(256, 2) void k1_ln_q(
    const float* __restrict__ regs,
    const float* __restrict__ gamma,
    const float* __restrict__ beta,
    const float* __restrict__ Wq,
    const float* __restrict__ bq)
{
    extern __shared__ float dsm[];
    float (*sx)[772] = (float(*)[772])dsm;       // 8 x 772
    float* sw = dsm + 8 * 772;                   // 768 x SW_PAD

    __shared__ __align__(16) float spart[8][8][16];  // [warp][row][col]
    __shared__ float s_mu[8], s_rs[8];

    const int t  = threadIdx.x;
    const int ct = blockIdx.x;     // 0..7  (16 cols)
    const int rt = blockIdx.y;     // 0..31 (8 rows)
    const int warp = t >> 5, lane = t & 31;

    // stage 8 input rows AND the W tile (independent loads, all in flight)
    {
        const float4* src = (const float4*)(regs + (size_t)rt * 8 * DDIM);
#pragma unroll
        for (int k = 0; k < 6; k++) {
            const int idx = t + k * 256;            // 0..1535
            const int r = idx / 192, j = idx % 192;
            *(float4*)&sx[r][j * 4] = src[idx];
        }
        // W tile: 768 x 16 -> 3072 float4, 12 per thread
#pragma unroll
        for (int k = 0; k < 12; k++) {
            const int idx = t + k * 256;            // 0..3071
            const int d = idx >> 2, c4 = idx & 3;
            const float4 w = *(const float4*)&Wq[(size_t)d * KD + ct * 16 + c4 * 4];
            *(float4*)&sw[d * SW_PAD + c4 * 4] = w;
        }
    }
    __syncthreads();

    // LN stats: warp w handles row w, one pass (sum + sumsq)
    {
        float s = 0.f, q = 0.f;
        for (int i = lane; i < DDIM; i += 32) {
            const float xv = sx[warp][i];
            s += xv;
            q += xv * xv;
        }
#pragma unroll
        for (int o = 16; o; o >>= 1) {
            s += __shfl_xor_sync(0xffffffffu, s, o);
            q += __shfl_xor_sync(0xffffffffu, q, o);
        }
        if (lane == 0) {
            const float mu  = s * (1.0f / DDIM);
            const float var = q * (1.0f / DDIM) - mu * mu;
            s_mu[warp] = mu;
            s_rs[warp] = rsqrtf(var + 1e-5f);
        }
    }
    __syncthreads();

    // normalize in place
    {
        const float g0 = gamma[t], g1 = gamma[t + 256], g2 = gamma[t + 512];
        const float b0 = beta[t],  b1 = beta[t + 256],  b2 = beta[t + 512];
#pragma unroll
        for (int r = 0; r < 8; r++) {
            const float mu = s_mu[r], rs = s_rs[r];
            sx[r][t      ] = (sx[r][t      ] - mu) * rs * g0 + b0;
            sx[r][t + 256] = (sx[r][t + 256] - mu) * rs * g1 + b1;
            sx[r][t + 512] = (sx[r][t + 512] - mu) * rs * g2 + b2;
        }
    }
    __syncthreads();

    // GEMM (smem-only): thread (c4 = t&3, ds = t>>2); d slice of 12, all 8 rows
    {
        const int c4 = t & 3;
        const int ds = t >> 2;
        const int d0 = ds * 12;
        const float* wp = sw + (size_t)d0 * SW_PAD + c4 * 4;

        float acc[8][4];
#pragma unroll
        for (int r = 0; r < 8; r++)
#pragma unroll
            for (int c = 0; c < 4; c++) acc[r][c] = 0.f;

#pragma unroll
        for (int j4 = 0; j4 < 3; j4++) {
            const int db = j4 * 4;
            const float4 w0 = *(const float4*)(wp + (size_t)(db + 0) * SW_PAD);
            const float4 w1 = *(const float4*)(wp + (size_t)(db + 1) * SW_PAD);
            const float4 w2 = *(const float4*)(wp + (size_t)(db + 2) * SW_PAD);
            const float4 w3 = *(const float4*)(wp + (size_t)(db + 3) * SW_PAD);
#pragma unroll
            for (int r = 0; r < 8; r++) {
                const float4 xv = *(const float4*)&sx[r][d0 + db];
                acc[r][0] += xv.x * w0.x + xv.y * w1.x + xv.z * w2.x + xv.w * w3.x;
                acc[r][1] += xv.x * w0.y + xv.y * w1.y + xv.z * w2.y + xv.w * w3.y;
                acc[r][2] += xv.x * w0.z + xv.y * w1.z + xv.z * w2.z + xv.w * w3.z;
                acc[r][3] += xv.x * w0.w + xv.y * w1.w + xv.z * w2.w + xv.w * w3.w;
            }
        }

        // in-warp reduce across the 8 dslices this warp owns (lane stride 4)
#pragma unroll
        for (int r = 0; r < 8; r++)
#pragma unroll
            for (int c = 0; c < 4; c++) {
                float v = acc[r][c];
                v += __shfl_xor_sync(0xffffffffu, v, 4);
                v += __shfl_xor_sync(0xffffffffu, v, 8);
                v += __shfl_xor_sync(0xffffffffu, v, 16);
                acc[r][c] = v;
            }
        if (lane < 4) {
#pragma unroll
            for (int r = 0; r < 8; r++)
                *(float4*)&spart[warp][r][lane * 4] =
                    make_float4(acc[r][0], acc[r][1], acc[r][2], acc[r][3]);
        }
    }
    __syncthreads();

    if (t < 128) {
        const int r = t >> 4, c = t & 15;
        float sum = bq[ct * 16 + c];
#pragma unroll
        for (int k = 0; k < 8; k++) sum += spart[k][r][c];
        g_q[(size_t)(rt * 8 + r) * KD + ct * 16 + c] = sum;
    }
}

// ---------------------------------------------------------------------------
// KB: merged scores+candidate-topk (blocks 0..127) + query_projected (128..223)
// 224 blocks total -> single wave at occupancy 2 on 148 SMs
// ---------------------------------------------------------------------------
__global__ __launch_bounds__(256, 2) void kb_scores_qp(
    const float* __restrict__ row_keys,
    const float* __restrict__ col_keys,
    const float* __restrict__ Wqc,
    const float* __restrict__ bqc,
    float* __restrict__ out)
{
    __shared__ float sk[64][66];   // role A: keys, d-major
    __shared__ float sq[32][64];   // role A: q halves
    __shared__ float ss[32][66];   // role A: scores (rows x keys), padded
    __shared__ float sqb[16][KD];  // role B

    const int t = threadIdx.x;
    const int b = blockIdx.x;
    const int warp = t >> 5, lane = t & 31;

    if (b < 128) {
        // ---- role A: scores = q_half @ keys^T  (64 keys x 32 rows) ----
        const int kt   = b & 7;          // 0..7
        const int rt   = (b >> 3) & 7;   // 0..7 (32 rows)
        const int side = b >> 6;         // 0..1
        const float* keys = side ? col_keys : row_keys;

        // stage keys transposed: sk[d][key]
        {
            const int d  = t & 63;
            const int k0 = t >> 6;       // 0..3
#pragma unroll
            for (int k = 0; k < 16; k++) {
                const int kl = k0 + k * 4;
                const int kg = kt * 64 + kl;
                sk[d][kl] = (kg < NK) ? keys[(size_t)kg * 64 + d] : 0.f;
            }
        }
        // stage q tile (32 rows x 64 half-dims)
#pragma unroll
        for (int k = 0; k < 8; k++) {
            const int idx = t + k * 256;
            const int r = idx >> 6, d = idx & 63;
            sq[r][d] = g_q[(size_t)(rt * 32 + r) * KD + side * 64 + d];
        }
        __syncthreads();

        const int kx = t & 31;           // key pair -> keys 2kx, 2kx+1
        const int rg = warp;             // rows 4rg..4rg+3
        float a0x = 0.f, a0y = 0.f, a1x = 0.f, a1y = 0.f;
        float a2x = 0.f, a2y = 0.f, a3x = 0.f, a3y = 0.f;
#pragma unroll 8
        for (int d = 0; d < 64; d++) {
            const float2 kv = *(const float2*)&sk[d][2 * kx];
            const float q0 = sq[4 * rg + 0][d];
            const float q1 = sq[4 * rg + 1][d];
            const float q2 = sq[4 * rg + 2][d];
            const float q3 = sq[4 * rg + 3][d];
            a0x += q0 * kv.x; a0y += q0 * kv.y;
            a1x += q1 * kv.x; a1y += q1 * kv.y;
            a2x += q2 * kv.x; a2y += q2 * kv.y;
            a3x += q3 * kv.x; a3y += q3 * kv.y;
        }
        // park scores in smem
        *(float2*)&ss[4 * rg + 0][2 * kx] = make_float2(a0x, a0y);
        *(float2*)&ss[4 * rg + 1][2 * kx] = make_float2(a1x, a1y);
        *(float2*)&ss[4 * rg + 2][2 * kx] = make_float2(a2x, a2y);
        *(float2*)&ss[4 * rg + 3][2 * kx] = make_float2(a3x, a3y);
        __syncthreads();

        // per-row top-4 extraction: warp w -> rows 4w..4w+3 (8 lanes per row)
        {
            const int rl    = lane >> 3;         // row within warp's group
            const int kslot = lane & 7;          // 8 keys per lane
            const int row_l = 4 * warp + rl;     // local row 0..31
            unsigned long long v[4] = {0ull, 0ull, 0ull, 0ull};
            const float* sp = &ss[row_l][kslot * 8];
#pragma unroll
            for (int j = 0; j < 8; j++) {
                const int kg = kt * 64 + kslot * 8 + j;
                if (kg < NK) insert4u(v, packcand(sp[j], kg));
            }
            // merge sorted-4 lists across the 8 lanes of this row group
#pragma unroll
            for (int off = 4; off >= 1; off >>= 1) {
                unsigned long long o[4];
#pragma unroll
                for (int j = 0; j < 4; j++)
                    o[j] = __shfl_down_sync(0xffffffffu, v[j], off, 8);
                if (kslot < off) {
#pragma unroll
                    for (int j = 0; j < 4; j++) insert4u(v, o[j]);
                }
            }
            if (kslot == 0) {
                const int row_g = rt * 32 + row_l;
#pragma unroll
                for (int n = 0; n < 4; n++)
                    g_cand[side][row_g][kt * 4 + n] = v[n];
            }
        }
    } else {
        // ---- role B: query_projected = q @ Wqc + bqc (16 rows x 128 cols) ----
        const int b2 = b - 128;          // 0..95
        const int ct = b2 % 6;           // 128-col tile
        const int rt = b2 / 6;           // 16-row tile

#pragma unroll
        for (int k = 0; k < 8; k++) {
            const int idx = t + k * 256;
            const int r = idx >> 7, d = idx & 127;
            sqb[r][d] = g_q[(size_t)(rt * 16 + r) * KD + d];
        }
        __syncthreads();

        const int tx = t & 63;           // col pair
        const int ty = t >> 6;           // 0..3 -> 4 rows each
        const int col = ct * 128 + tx * 2;
        const int r0 = ty * 4;
        float a00 = 0.f, a01 = 0.f, a10 = 0.f, a11 = 0.f;
        float a20 = 0.f, a21 = 0.f, a30 = 0.f, a31 = 0.f;
#pragma unroll 16
        for (int d = 0; d < KD; d++) {
            const float2 w = *(const float2*)&Wqc[(size_t)d * DDIM + col];
            const float q0 = sqb[r0 + 0][d];
            const float q1 = sqb[r0 + 1][d];
            const float q2 = sqb[r0 + 2][d];
            const float q3 = sqb[r0 + 3][d];
            a00 += q0 * w.x; a01 += q0 * w.y;
            a10 += q1 * w.x; a11 += q1 * w.y;
            a20 += q2 * w.x; a21 += q2 * w.y;
            a30 += q3 * w.x; a31 += q3 * w.y;
        }
        const float2 bb = *(const float2*)&bqc[col];
        const int grow = rt * 16 + r0;
        float* o = out + QP_OFF + (size_t)grow * DDIM + col;
        *(float2*)(o + 0 * DDIM) = make_float2(a00 + bb.x, a01 + bb.y);
        *(float2*)(o + 1 * DDIM) = make_float2(a10 + bb.x, a11 + bb.y);
        *(float2*)(o + 2 * DDIM) = make_float2(a20 + bb.x, a21 + bb.y);
        *(float2*)(o + 3 * DDIM) = make_float2(a30 + bb.x, a31 + bb.y);
    }
}

// ---------------------------------------------------------------------------
// KC: reduce 32 candidates per side, combine 4x4, write, gather
// grid 256 (one row), 256 threads
// ---------------------------------------------------------------------------
__global__ __launch_bounds__(256) void kc_topk_gather(
    const float* __restrict__ concepts,
    float* __restrict__ out)
{
    __shared__ unsigned long long s_top[2][TK];
    __shared__ int s_idx[TK];

    const int row  = blockIdx.x;
    const int t    = threadIdx.x;
    const int warp = t >> 5, lane = t & 31;

    // warps 0/1: per-side top-4 by 4-round u64 max extraction over 32 candidates
    if (warp < 2) {
        const int side = warp;
        unsigned long long c = g_cand[side][row][lane];
#pragma unroll
        for (int n = 0; n < TK; n++) {
            unsigned long long m = c;
#pragma unroll
            for (int off = 16; off >= 1; off >>= 1) {
                unsigned long long o = __shfl_xor_sync(0xffffffffu, m, off);
                if (o > m) m = o;
            }
            if (lane == 0) s_top[side][n] = m;
            if (c == m) c = 0ull;
        }
    }
    __syncthreads();

    // warp 2: 4x4 combine on 16 lanes, 4-round extraction
    if (warp == 2) {
        unsigned long long c = 0ull;
        if (lane < 16) {
            const unsigned long long r4 = s_top[0][lane >> 2];
            const unsigned long long c4 = s_top[1][lane & 3];
            const float sum = unpackval(r4) + unpackval(c4);
            const int flat  = unpackidx(r4) * NK + unpackidx(c4);
            c = packcand(sum, flat);
        }
#pragma unroll
        for (int n = 0; n < TK; n++) {
            unsigned long long m = c;
#pragma unroll
            for (int off = 16; off >= 1; off >>= 1) {
                unsigned long long o = __shfl_xor_sync(0xffffffffu, m, off);
                if (o > m) m = o;
            }
            if (lane == 0) {
                out[SC_OFF  + row * TK + n] = unpackval(m);
                const int fi = unpackidx(m);
                out[IDX_OFF + row * TK + n] = (float)fi;
                s_idx[n] = fi;
            }
            if (c == m) c = 0ull;
        }
    }
    __syncthreads();

    // gather 4 concept rows (4 x 192 float4), 3 per thread
#pragma unroll
    for (int k = 0; k < 3; k++) {
        const int i = t + k * 256;
        const int n = i / 192, j = i % 192;
        const int cid = s_idx[n];
        const float4 val = ((const float4*)concepts)[(size_t)cid * 192 + j];
        ((float4*)(out + OC_OFF))[(size_t)(row * TK + n) * 192 + j] = val;
    }
}

extern "C" void kernel_launch(void* const* d_in, const int* in_sizes, int n_in,
                              void* d_out, int out_size) {
    const float* regs     = (const float*)d_in[0];
    const float* row_keys = (const float*)d_in[1];
    const float* col_keys = (const float*)d_in[2];
    const float* concepts = (const float*)d_in[3];
    const float* gamma    = (const float*)d_in[4];
    const float* beta     = (const float*)d_in[5];
    const float* Wq       = (const float*)d_in[6];
    const float* bq       = (const float*)d_in[7];
    const float* Wqc      = (const float*)d_in[8];
    const float* bqc      = (const float*)d_in[9];
    float* out = (float*)d_out;

    static int s_attr_done = 0;
    if (!s_attr_done) {
        cudaFuncSetAttribute(k1_ln_q, cudaFuncAttributeMaxDynamicSharedMemorySize,
                             K1_DSMEM);
        s_attr_done = 1;
    }

    k1_ln_q<<<dim3(8, 32), 256, K1_DSMEM>>>(regs, gamma, beta, Wq, bq);
    kb_scores_qp<<<224, 256>>>(row_keys, col_keys, Wqc, bqc, out);
    kc_topk_gather<<<256, 256>>>(concepts, out);
}

// round 16
// speedup vs baseline: 1.1013x; 1.1013x over previous
#include <cuda_runtime.h>
#include <cstdint>

#define NROWS 256
#define DDIM  768
#define KD    128
#define NK    500
#define TK    4
#define NBLK  256

// output layout (float32, reference return order)
#define OC_OFF  0
#define IDX_OFF 786432
#define SC_OFF  787456
#define QP_OFF  788480

#define NEG_INF (-3.402823466e38f)

__device__ float g_q[NROWS * KD];                      // queries
__device__ unsigned long long g_cand[2][NROWS][32];    // per (side,row): 8 tiles x top-4
__device__ unsigned g_bar[2];                          // monotonic grid barriers

// ---- packed candidate: sortable float in high 32, ~idx in low 32 ----
__device__ __forceinline__ unsigned long long packcand(float f, int idx) {
    unsigned int b = __float_as_uint(f);
    unsigned int s = (b & 0x80000000u) ? ~b : (b | 0x80000000u);
    return ((unsigned long long)s << 32) | (unsigned int)(~idx);
}
__device__ __forceinline__ float unpackval(unsigned long long c) {
    unsigned int s = (unsigned int)(c >> 32);
    unsigned int b = (s & 0x80000000u) ? (s & 0x7FFFFFFFu) : ~s;
    return __uint_as_float(b);
}
__device__ __forceinline__ int unpackidx(unsigned long long c) {
    return (int)(~(unsigned int)(c & 0xFFFFFFFFu));
}

__device__ __forceinline__ void insert4u(unsigned long long* v, unsigned long long x) {
    if (x <= v[3]) return;
    v[3] = x;
    if (v[3] > v[2]) { unsigned long long tt = v[3]; v[3] = v[2]; v[2] = tt; }
    if (v[2] > v[1]) { unsigned long long tt = v[2]; v[2] = v[1]; v[1] = tt; }
    if (v[1] > v[0]) { unsigned long long tt = v[1]; v[1] = v[0]; v[0] = tt; }
}

// grid-wide barrier: monotonic counter, replay-safe, all NBLK blocks resident
__device__ __forceinline__ void gridbar(int b) {
    __syncthreads();
    if (threadIdx.x == 0) {
        __threadfence();
        unsigned my = atomicAdd(&g_bar[b], 1u) + 1u;
        unsigned target = ((my + NBLK - 1u) / NBLK) * NBLK;
        while (*(volatile unsigned*)&g_bar[b] < target) { }
        __threadfence();
    }
    __syncthreads();
}

// shared memory union across phases
struct SmemP1 {
    float sx[8][772];
    float spart[8][8][16];
    float mu[8], rs[8];
};
struct SmemA {
    float sk[64][66];
    float sq[32][64];
    float ss[32][66];
};
struct SmemB { float sqb[16][KD]; };
struct SmemP3 {
    unsigned long long s_top[2][TK];
    int s_idx[TK];
};
union SmemU {
    SmemP1 p1;
    SmemA  a;
    SmemB  b;
    SmemP3 p3;
};

__global__ __launch_bounds__(256, 2) void fused_all(
    const float* __restrict__ regs,
    const float* __restrict__ row_keys,
    const float* __restrict__ col_keys,
    const float* __restrict__ concepts,
    const float* __restrict__ gamma,
    const float* __restrict__ beta,
    const float* __restrict__ Wq,
    const float* __restrict__ bq,
    const float* __restrict__ Wqc,
    const float* __restrict__ bqc,
    float* __restrict__ out)
{
    __shared__ SmemU u;

    const int t    = threadIdx.x;
    const int blk  = blockIdx.x;
    const int warp = t >> 5, lane = t & 31;

    // ======================= PHASE 1: LN + Q GEMM =========================
    {
        const int ct = blk & 7;        // 0..7  (16 cols)
        const int rt = blk >> 3;       // 0..31 (8 rows)

        // stage 8 input rows
        {
            const float4* src = (const float4*)(regs + (size_t)rt * 8 * DDIM);
#pragma unroll
            for (int k = 0; k < 6; k++) {
                const int idx = t + k * 256;            // 0..1535
                const int r = idx / 192, j = idx % 192;
                *(float4*)&u.p1.sx[r][j * 4] = src[idx];
            }
        }
        __syncthreads();

        // LN stats: warp w handles row w, one pass
        {
            float s = 0.f, q = 0.f;
            for (int i = lane; i < DDIM; i += 32) {
                const float xv = u.p1.sx[warp][i];
                s += xv;
                q += xv * xv;
            }
#pragma unroll
            for (int o = 16; o; o >>= 1) {
                s += __shfl_xor_sync(0xffffffffu, s, o);
                q += __shfl_xor_sync(0xffffffffu, q, o);
            }
            if (lane == 0) {
                const float mu  = s * (1.0f / DDIM);
                const float var = q * (1.0f / DDIM) - mu * mu;
                u.p1.mu[warp] = mu;
                u.p1.rs[warp] = rsqrtf(var + 1e-5f);
            }
        }
        __syncthreads();

        // normalize in place
        {
            const float g0 = gamma[t], g1 = gamma[t + 256], g2 = gamma[t + 512];
            const float b0 = beta[t],  b1 = beta[t + 256],  b2 = beta[t + 512];
#pragma unroll
            for (int r = 0; r < 8; r++) {
                const float mu = u.p1.mu[r], rs = u.p1.rs[r];
                u.p1.sx[r][t      ] = (u.p1.sx[r][t      ] - mu) * rs * g0 + b0;
                u.p1.sx[r][t + 256] = (u.p1.sx[r][t + 256] - mu) * rs * g1 + b1;
                u.p1.sx[r][t + 512] = (u.p1.sx[r][t + 512] - mu) * rs * g2 + b2;
            }
        }
        __syncthreads();

        // GEMM: thread (c4 = t&3, ds = t>>2 in [0,64)); d slice of 12, all 8 rows
        {
            const int c4 = t & 3;
            const int ds = t >> 2;
            const int d0 = ds * 12;
            const float* wp = Wq + (size_t)d0 * KD + ct * 16 + c4 * 4;

            float acc[8][4];
#pragma unroll
            for (int r = 0; r < 8; r++)
#pragma unroll
                for (int c = 0; c < 4; c++) acc[r][c] = 0.f;

#pragma unroll
            for (int j4 = 0; j4 < 3; j4++) {
                const int db = j4 * 4;
                const float4 w0 = *(const float4*)(wp + (size_t)(db + 0) * KD);
                const float4 w1 = *(const float4*)(wp + (size_t)(db + 1) * KD);
                const float4 w2 = *(const float4*)(wp + (size_t)(db + 2) * KD);
                const float4 w3 = *(const float4*)(wp + (size_t)(db + 3) * KD);
#pragma unroll
                for (int r = 0; r < 8; r++) {
                    const float4 xv = *(const float4*)&u.p1.sx[r][d0 + db];
                    acc[r][0] += xv.x * w0.x + xv.y * w1.x + xv.z * w2.x + xv.w * w3.x;
                    acc[r][1] += xv.x * w0.y + xv.y * w1.y + xv.z * w2.y + xv.w * w3.y;
                    acc[r][2] += xv.x * w0.z + xv.y * w1.z + xv.z * w2.z + xv.w * w3.z;
                    acc[r][3] += xv.x * w0.w + xv.y * w1.w + xv.z * w2.w + xv.w * w3.w;
                }
            }

            // in-warp reduce across the 8 dslices this warp owns (lane stride 4)
#pragma unroll
            for (int r = 0; r < 8; r++)
#pragma unroll
                for (int c = 0; c < 4; c++) {
                    float v = acc[r][c];
                    v += __shfl_xor_sync(0xffffffffu, v, 4);
                    v += __shfl_xor_sync(0xffffffffu, v, 8);
                    v += __shfl_xor_sync(0xffffffffu, v, 16);
                    acc[r][c] = v;
                }
            if (lane < 4) {
#pragma unroll
                for (int r = 0; r < 8; r++)
                    *(float4*)&u.p1.spart[warp][r][lane * 4] =
                        make_float4(acc[r][0], acc[r][1], acc[r][2], acc[r][3]);
            }
        }
        __syncthreads();

        if (t < 128) {
            const int r = t >> 4, c = t & 15;
            float sum = bq[ct * 16 + c];
#pragma unroll
            for (int k = 0; k < 8; k++) sum += u.p1.spart[k][r][c];
            g_q[(size_t)(rt * 8 + r) * KD + ct * 16 + c] = sum;
        }
    }

    gridbar(0);

    // ================ PHASE 2: scores+cand (A) / qp GEMM (B) ==============
    if (blk < 128) {
        // ---- role A: scores = q_half @ keys^T  (64 keys x 32 rows) ----
        const int kt   = blk & 7;
        const int rt   = (blk >> 3) & 7;
        const int side = blk >> 6;
        const float* keys = side ? col_keys : row_keys;

        {
            const int d  = t & 63;
            const int k0 = t >> 6;
#pragma unroll
            for (int k = 0; k < 16; k++) {
                const int kl = k0 + k * 4;
                const int kg = kt * 64 + kl;
                u.a.sk[d][kl] = (kg < NK) ? keys[(size_t)kg * 64 + d] : 0.f;
            }
        }
#pragma unroll
        for (int k = 0; k < 8; k++) {
            const int idx = t + k * 256;
            const int r = idx >> 6, d = idx & 63;
            u.a.sq[r][d] = g_q[(size_t)(rt * 32 + r) * KD + side * 64 + d];
        }
        __syncthreads();

        const int kx = t & 31;
        const int rg = warp;
        float a0x = 0.f, a0y = 0.f, a1x = 0.f, a1y = 0.f;
        float a2x = 0.f, a2y = 0.f, a3x = 0.f, a3y = 0.f;
#pragma unroll 8
        for (int d = 0; d < 64; d++) {
            const float2 kv = *(const float2*)&u.a.sk[d][2 * kx];
            const float q0 = u.a.sq[4 * rg + 0][d];
            const float q1 = u.a.sq[4 * rg + 1][d];
            const float q2 = u.a.sq[4 * rg + 2][d];
            const float q3 = u.a.sq[4 * rg + 3][d];
            a0x += q0 * kv.x; a0y += q0 * kv.y;
            a1x += q1 * kv.x; a1y += q1 * kv.y;
            a2x += q2 * kv.x; a2y += q2 * kv.y;
            a3x += q3 * kv.x; a3y += q3 * kv.y;
        }
        *(float2*)&u.a.ss[4 * rg + 0][2 * kx] = make_float2(a0x, a0y);
        *(float2*)&u.a.ss[4 * rg + 1][2 * kx] = make_float2(a1x, a1y);
        *(float2*)&u.a.ss[4 * rg + 2][2 * kx] = make_float2(a2x, a2y);
        *(float2*)&u.a.ss[4 * rg + 3][2 * kx] = make_float2(a3x, a3y);
        __syncthreads();

        // per-row top-4 extraction: warp w -> rows 4w..4w+3 (8 lanes per row)
        {
            const int rl    = lane >> 3;
            const int kslot = lane & 7;
            const int row_l = 4 * warp + rl;
            unsigned long long v[4] = {0ull, 0ull, 0ull, 0ull};
            const float* sp = &u.a.ss[row_l][kslot * 8];
#pragma unroll
            for (int j = 0; j < 8; j++) {
                const int kg = kt * 64 + kslot * 8 + j;
                if (kg < NK) insert4u(v, packcand(sp[j], kg));
            }
#pragma unroll
            for (int off = 4; off >= 1; off >>= 1) {
                unsigned long long o[4];
#pragma unroll
                for (int j = 0; j < 4; j++)
                    o[j] = __shfl_down_sync(0xffffffffu, v[j], off, 8);
                if (kslot < off) {
#pragma unroll
                    for (int j = 0; j < 4; j++) insert4u(v, o[j]);
                }
            }
            if (kslot == 0) {
                const int row_g = rt * 32 + row_l;
#pragma unroll
                for (int n = 0; n < 4; n++)
                    g_cand[side][row_g][kt * 4 + n] = v[n];
            }
        }
    } else if (blk < 224) {
        // ---- role B: query_projected = q @ Wqc + bqc (16 rows x 128 cols) ----
        const int b2 = blk - 128;        // 0..95
        const int ct = b2 % 6;
        const int rt = b2 / 6;

#pragma unroll
        for (int k = 0; k < 8; k++) {
            const int idx = t + k * 256;
            const int r = idx >> 7, d = idx & 127;
            u.b.sqb[r][d] = g_q[(size_t)(rt * 16 + r) * KD + d];
        }
        __syncthreads();

        const int tx = t & 63;
        const int ty = t >> 6;
        const int col = ct * 128 + tx * 2;
        const int r0 = ty * 4;
        float a00 = 0.f, a01 = 0.f, a10 = 0.f, a11 = 0.f;
        float a20 = 0.f, a21 = 0.f, a30 = 0.f, a31 = 0.f;
#pragma unroll 16
        for (int d = 0; d < KD; d++) {
            const float2 w = *(const float2*)&Wqc[(size_t)d * DDIM + col];
            const float q0 = u.b.sqb[r0 + 0][d];
            const float q1 = u.b.sqb[r0 + 1][d];
            const float q2 = u.b.sqb[r0 + 2][d];
            const float q3 = u.b.sqb[r0 + 3][d];
            a00 += q0 * w.x; a01 += q0 * w.y;
            a10 += q1 * w.x; a11 += q1 * w.y;
            a20 += q2 * w.x; a21 += q2 * w.y;
            a30 += q3 * w.x; a31 += q3 * w.y;
        }
        const float2 bb = *(const float2*)&bqc[col];
        const int grow = rt * 16 + r0;
        float* o = out + QP_OFF + (size_t)grow * DDIM + col;
        *(float2*)(o + 0 * DDIM) = make_float2(a00 + bb.x, a01 + bb.y);
        *(float2*)(o + 1 * DDIM) = make_float2(a10 + bb.x, a11 + bb.y);
        *(float2*)(o + 2 * DDIM) = make_float2(a20 + bb.x, a21 + bb.y);
        *(float2*)(o + 3 * DDIM) = make_float2(a30 + bb.x, a31 + bb.y);
    }

    gridbar(1);

    // ================ PHASE 3: topk reduce + combine + gather ==============
    {
        const int row = blk;

        if (warp < 2) {
            const int side = warp;
            unsigned long long c = g_cand[side][row][lane];
#pragma unroll
            for (int n = 0; n < TK; n++) {
                unsigned long long m = c;
#pragma unroll
                for (int off = 16; off >= 1; off >>= 1) {
                    unsigned long long o = __shfl_xor_sync(0xffffffffu, m, off);
                    if (o > m) m = o;
                }
                if (lane == 0) u.p3.s_top[side][n] = m;
                if (c == m) c = 0ull;
            }
        }
        __syncthreads();

        if (warp == 2) {
            unsigned long long c = 0ull;
            if (lane < 16) {
                const unsigned long long r4 = u.p3.s_top[0][lane >> 2];
                const unsigned long long c4 = u.p3.s_top[1][lane & 3];
                const float sum = unpackval(r4) + unpackval(c4);
                const int flat  = unpackidx(r4) * NK + unpackidx(c4);
                c = packcand(sum, flat);
            }
#pragma unroll
            for (int n = 0; n < TK; n++) {
                unsigned long long m = c;
#pragma unroll
                for (int off = 16; off >= 1; off >>= 1) {
                    unsigned long long o = __shfl_xor_sync(0xffffffffu, m, off);
                    if (o > m) m = o;
                }
                if (lane == 0) {
                    out[SC_OFF  + row * TK + n] = unpackval(m);
                    const int fi = unpackidx(m);
                    out[IDX_OFF + row * TK + n] = (float)fi;
                    u.p3.s_idx[n] = fi;
                }
                if (c == m) c = 0ull;
            }
        }
        __syncthreads();

        // gather 4 concept rows (4 x 192 float4), 3 per thread
#pragma unroll
        for (int k = 0; k < 3; k++) {
            const int i = t + k * 256;
            const int n = i / 192, j = i % 192;
            const int cid = u.p3.s_idx[n];
            const float4 val = ((const float4*)concepts)[(size_t)cid * 192 + j];
            ((float4*)(out + OC_OFF))[(size_t)(row * TK + n) * 192 + j] = val;
        }
    }
}

extern "C" void kernel_launch(void* const* d_in, const int* in_sizes, int n_in,
                              void* d_out, int out_size) {
    const float* regs     = (const float*)d_in[0];
    const float* row_keys = (const float*)d_in[1];
    const float* col_keys = (const float*)d_in[2];
    const float* concepts = (const float*)d_in[3];
    const float* gamma    = (const float*)d_in[4];
    const float* beta     = (const float*)d_in[5];
    const float* Wq       = (const float*)d_in[6];
    const float* bq       = (const float*)d_in[7];
    const float* Wqc      = (const float*)d_in[8];
    const float* bqc      = (const float*)d_in[9];
    float* out = (float*)d_out;

    fused_all<<<NBLK, 256>>>(regs, row_keys, col_keys, concepts, gamma, beta,
                             Wq, bq, Wqc, bqc, out);
}

// round 17
// speedup vs baseline: 1.1218x; 1.0186x over previous
#include <cuda_runtime.h>
#include <cstdint>

#define NROWS 256
#define DDIM  768
#define KD    128
#define NK    500
#define TK    4
#define NBLK  256

// output layout (float32, reference return order)
#define OC_OFF  0
#define IDX_OFF 786432
#define SC_OFF  787456
#define QP_OFF  788480

#define NEG_INF (-3.402823466e38f)

__device__ float g_q[NROWS * KD];                      // queries
__device__ unsigned long long g_cand[2][NROWS][32];    // per (side,row): 8 tiles x top-4
__device__ unsigned g_seq;                             // monotonic launch sequence
__device__ unsigned g_cnt1[32];                        // P1 rowtile (8 rows) done counts
__device__ unsigned g_cnt2[8];                         // role-A rowtile (32 rows) done counts

// ---- packed candidate: sortable float in high 32, ~idx in low 32 ----
__device__ __forceinline__ unsigned long long packcand(float f, int idx) {
    unsigned int b = __float_as_uint(f);
    unsigned int s = (b & 0x80000000u) ? ~b : (b | 0x80000000u);
    return ((unsigned long long)s << 32) | (unsigned int)(~idx);
}
__device__ __forceinline__ float unpackval(unsigned long long c) {
    unsigned int s = (unsigned int)(c >> 32);
    unsigned int b = (s & 0x80000000u) ? (s & 0x7FFFFFFFu) : ~s;
    return __uint_as_float(b);
}
__device__ __forceinline__ int unpackidx(unsigned long long c) {
    return (int)(~(unsigned int)(c & 0xFFFFFFFFu));
}

__device__ __forceinline__ void insert4u(unsigned long long* v, unsigned long long x) {
    if (x <= v[3]) return;
    v[3] = x;
    if (v[3] > v[2]) { unsigned long long tt = v[3]; v[3] = v[2]; v[2] = tt; }
    if (v[2] > v[1]) { unsigned long long tt = v[2]; v[2] = v[1]; v[1] = tt; }
    if (v[1] > v[0]) { unsigned long long tt = v[1]; v[1] = v[0]; v[0] = tt; }
}

__device__ __forceinline__ void waitcnt(volatile unsigned* p, unsigned tgt) {
    while (*p < tgt) { }
    __threadfence();
}

// shared memory union across phases
struct SmemP1 {
    float sx[8][772];
    float spart[8][8][16];
    float mu[8], rs[8];
};
struct SmemA {
    float sk[64][66];
    float sq[32][64];
    float ss[32][66];
};
struct SmemB { float sqb[16][KD]; };
struct SmemP3 {
    unsigned long long s_top[2][TK];
    int s_idx[TK];
};
union SmemU {
    SmemP1 p1;
    SmemA  a;
    SmemB  b;
    SmemP3 p3;
};

__global__ __launch_bounds__(256, 2) void fused_all(
    const float* __restrict__ regs,
    const float* __restrict__ row_keys,
    const float* __restrict__ col_keys,
    const float* __restrict__ concepts,
    const float* __restrict__ gamma,
    const float* __restrict__ beta,
    const float* __restrict__ Wq,
    const float* __restrict__ bq,
    const float* __restrict__ Wqc,
    const float* __restrict__ bqc,
    float* __restrict__ out)
{
    __shared__ SmemU u;
    __shared__ unsigned s_epoch;

    const int t    = threadIdx.x;
    const int blk  = blockIdx.x;
    const int warp = t >> 5, lane = t & 31;

    if (t == 0) s_epoch = atomicAdd(&g_seq, 1u) / (unsigned)NBLK;

    // ======================= PHASE 1: LN + Q GEMM =========================
    {
        const int ct = blk & 7;        // 0..7  (16 cols)
        const int rt = blk >> 3;       // 0..31 (8 rows)

        // stage 8 input rows
        {
            const float4* src = (const float4*)(regs + (size_t)rt * 8 * DDIM);
#pragma unroll
            for (int k = 0; k < 6; k++) {
                const int idx = t + k * 256;            // 0..1535
                const int r = idx / 192, j = idx % 192;
                *(float4*)&u.p1.sx[r][j * 4] = src[idx];
            }
        }
        __syncthreads();

        // LN stats: warp w handles row w, one pass
        {
            float s = 0.f, q = 0.f;
            for (int i = lane; i < DDIM; i += 32) {
                const float xv = u.p1.sx[warp][i];
                s += xv;
                q += xv * xv;
            }
#pragma unroll
            for (int o = 16; o; o >>= 1) {
                s += __shfl_xor_sync(0xffffffffu, s, o);
                q += __shfl_xor_sync(0xffffffffu, q, o);
            }
            if (lane == 0) {
                const float mu  = s * (1.0f / DDIM);
                const float var = q * (1.0f / DDIM) - mu * mu;
                u.p1.mu[warp] = mu;
                u.p1.rs[warp] = rsqrtf(var + 1e-5f);
            }
        }
        __syncthreads();

        // normalize in place
        {
            const float g0 = gamma[t], g1 = gamma[t + 256], g2 = gamma[t + 512];
            const float b0 = beta[t],  b1 = beta[t + 256],  b2 = beta[t + 512];
#pragma unroll
            for (int r = 0; r < 8; r++) {
                const float mu = u.p1.mu[r], rs = u.p1.rs[r];
                u.p1.sx[r][t      ] = (u.p1.sx[r][t      ] - mu) * rs * g0 + b0;
                u.p1.sx[r][t + 256] = (u.p1.sx[r][t + 256] - mu) * rs * g1 + b1;
                u.p1.sx[r][t + 512] = (u.p1.sx[r][t + 512] - mu) * rs * g2 + b2;
            }
        }
        __syncthreads();

        // GEMM: thread (c4 = t&3, ds = t>>2 in [0,64)); d slice of 12, all 8 rows
        {
            const int c4 = t & 3;
            const int ds = t >> 2;
            const int d0 = ds * 12;
            const float* wp = Wq + (size_t)d0 * KD + ct * 16 + c4 * 4;

            float acc[8][4];
#pragma unroll
            for (int r = 0; r < 8; r++)
#pragma unroll
                for (int c = 0; c < 4; c++) acc[r][c] = 0.f;

#pragma unroll
            for (int j4 = 0; j4 < 3; j4++) {
                const int db = j4 * 4;
                const float4 w0 = *(const float4*)(wp + (size_t)(db + 0) * KD);
                const float4 w1 = *(const float4*)(wp + (size_t)(db + 1) * KD);
                const float4 w2 = *(const float4*)(wp + (size_t)(db + 2) * KD);
                const float4 w3 = *(const float4*)(wp + (size_t)(db + 3) * KD);
#pragma unroll
                for (int r = 0; r < 8; r++) {
                    const float4 xv = *(const float4*)&u.p1.sx[r][d0 + db];
                    acc[r][0] += xv.x * w0.x + xv.y * w1.x + xv.z * w2.x + xv.w * w3.x;
                    acc[r][1] += xv.x * w0.y + xv.y * w1.y + xv.z * w2.y + xv.w * w3.y;
                    acc[r][2] += xv.x * w0.z + xv.y * w1.z + xv.z * w2.z + xv.w * w3.z;
                    acc[r][3] += xv.x * w0.w + xv.y * w1.w + xv.z * w2.w + xv.w * w3.w;
                }
            }

            // in-warp reduce across the 8 dslices this warp owns (lane stride 4)
#pragma unroll
            for (int r = 0; r < 8; r++)
#pragma unroll
                for (int c = 0; c < 4; c++) {
                    float v = acc[r][c];
                    v += __shfl_xor_sync(0xffffffffu, v, 4);
                    v += __shfl_xor_sync(0xffffffffu, v, 8);
                    v += __shfl_xor_sync(0xffffffffu, v, 16);
                    acc[r][c] = v;
                }
            if (lane < 4) {
#pragma unroll
                for (int r = 0; r < 8; r++)
                    *(float4*)&u.p1.spart[warp][r][lane * 4] =
                        make_float4(acc[r][0], acc[r][1], acc[r][2], acc[r][3]);
            }
        }
        __syncthreads();

        if (t < 128) {
            const int r = t >> 4, c = t & 15;
            float sum = bq[ct * 16 + c];
#pragma unroll
            for (int k = 0; k < 8; k++) sum += u.p1.spart[k][r][c];
            g_q[(size_t)(rt * 8 + r) * KD + ct * 16 + c] = sum;
        }
        __syncthreads();
        if (t == 0) {
            __threadfence();
            atomicAdd(&g_cnt1[rt], 1u);
        }
    }

    const unsigned epoch = s_epoch;
    const unsigned tgt1  = (epoch + 1u) * 8u;    // 8 coltile blocks per P1 rowtile
    const unsigned tgt2  = (epoch + 1u) * 16u;   // 16 A-blocks per 32-row tile

    // ================ PHASE 2: scores+cand (A) / qp GEMM (B) ==============
    if (blk < 128) {
        // ---- role A: scores = q_half @ keys^T  (64 keys x 32 rows) ----
        const int kt   = blk & 7;
        const int rt   = (blk >> 3) & 7;
        const int side = blk >> 6;
        const float* keys = side ? col_keys : row_keys;

        // wait for the 4 P1 rowtiles covering rows rt*32..rt*32+31
        if (t < 4) waitcnt(&g_cnt1[rt * 4 + t], tgt1);
        __syncthreads();

        {
            const int d  = t & 63;
            const int k0 = t >> 6;
#pragma unroll
            for (int k = 0; k < 16; k++) {
                const int kl = k0 + k * 4;
                const int kg = kt * 64 + kl;
                u.a.sk[d][kl] = (kg < NK) ? keys[(size_t)kg * 64 + d] : 0.f;
            }
        }
#pragma unroll
        for (int k = 0; k < 8; k++) {
            const int idx = t + k * 256;
            const int r = idx >> 6, d = idx & 63;
            u.a.sq[r][d] = g_q[(size_t)(rt * 32 + r) * KD + side * 64 + d];
        }
        __syncthreads();

        const int kx = t & 31;
        const int rg = warp;
        float a0x = 0.f, a0y = 0.f, a1x = 0.f, a1y = 0.f;
        float a2x = 0.f, a2y = 0.f, a3x = 0.f, a3y = 0.f;
#pragma unroll 8
        for (int d = 0; d < 64; d++) {
            const float2 kv = *(const float2*)&u.a.sk[d][2 * kx];
            const float q0 = u.a.sq[4 * rg + 0][d];
            const float q1 = u.a.sq[4 * rg + 1][d];
            const float q2 = u.a.sq[4 * rg + 2][d];
            const float q3 = u.a.sq[4 * rg + 3][d];
            a0x += q0 * kv.x; a0y += q0 * kv.y;
            a1x += q1 * kv.x; a1y += q1 * kv.y;
            a2x += q2 * kv.x; a2y += q2 * kv.y;
            a3x += q3 * kv.x; a3y += q3 * kv.y;
        }
        *(float2*)&u.a.ss[4 * rg + 0][2 * kx] = make_float2(a0x, a0y);
        *(float2*)&u.a.ss[4 * rg + 1][2 * kx] = make_float2(a1x, a1y);
        *(float2*)&u.a.ss[4 * rg + 2][2 * kx] = make_float2(a2x, a2y);
        *(float2*)&u.a.ss[4 * rg + 3][2 * kx] = make_float2(a3x, a3y);
        __syncthreads();

        // per-row top-4 extraction: warp w -> rows 4w..4w+3 (8 lanes per row)
        {
            const int rl    = lane >> 3;
            const int kslot = lane & 7;
            const int row_l = 4 * warp + rl;
            unsigned long long v[4] = {0ull, 0ull, 0ull, 0ull};
            const float* sp = &u.a.ss[row_l][kslot * 8];
#pragma unroll
            for (int j = 0; j < 8; j++) {
                const int kg = kt * 64 + kslot * 8 + j;
                if (kg < NK) insert4u(v, packcand(sp[j], kg));
            }
#pragma unroll
            for (int off = 4; off >= 1; off >>= 1) {
                unsigned long long o[4];
#pragma unroll
                for (int j = 0; j < 4; j++)
                    o[j] = __shfl_down_sync(0xffffffffu, v[j], off, 8);
                if (kslot < off) {
#pragma unroll
                    for (int j = 0; j < 4; j++) insert4u(v, o[j]);
                }
            }
            if (kslot == 0) {
                const int row_g = rt * 32 + row_l;
#pragma unroll
                for (int n = 0; n < 4; n++)
                    g_cand[side][row_g][kt * 4 + n] = v[n];
            }
        }
        __syncthreads();
        if (t == 0) {
            __threadfence();
            atomicAdd(&g_cnt2[rt], 1u);
        }
    } else if (blk < 224) {
        // ---- role B: query_projected = q @ Wqc + bqc (16 rows x 128 cols) ----
        const int b2 = blk - 128;        // 0..95
        const int ct = b2 % 6;
        const int rt = b2 / 6;

        // wait for the 2 P1 rowtiles covering rows rt*16..rt*16+15
        if (t < 2) waitcnt(&g_cnt1[rt * 2 + t], tgt1);
        __syncthreads();

#pragma unroll
        for (int k = 0; k < 8; k++) {
            const int idx = t + k * 256;
            const int r = idx >> 7, d = idx & 127;
            u.b.sqb[r][d] = g_q[(size_t)(rt * 16 + r) * KD + d];
        }
        __syncthreads();

        const int tx = t & 63;
        const int ty = t >> 6;
        const int col = ct * 128 + tx * 2;
        const int r0 = ty * 4;
        float a00 = 0.f, a01 = 0.f, a10 = 0.f, a11 = 0.f;
        float a20 = 0.f, a21 = 0.f, a30 = 0.f, a31 = 0.f;
#pragma unroll 16
        for (int d = 0; d < KD; d++) {
            const float2 w = *(const float2*)&Wqc[(size_t)d * DDIM + col];
            const float q0 = u.b.sqb[r0 + 0][d];
            const float q1 = u.b.sqb[r0 + 1][d];
            const float q2 = u.b.sqb[r0 + 2][d];
            const float q3 = u.b.sqb[r0 + 3][d];
            a00 += q0 * w.x; a01 += q0 * w.y;
            a10 += q1 * w.x; a11 += q1 * w.y;
            a20 += q2 * w.x; a21 += q2 * w.y;
            a30 += q3 * w.x; a31 += q3 * w.y;
        }
        const float2 bb = *(const float2*)&bqc[col];
        const int grow = rt * 16 + r0;
        float* o = out + QP_OFF + (size_t)grow * DDIM + col;
        *(float2*)(o + 0 * DDIM) = make_float2(a00 + bb.x, a01 + bb.y);
        *(float2*)(o + 1 * DDIM) = make_float2(a10 + bb.x, a11 + bb.y);
        *(float2*)(o + 2 * DDIM) = make_float2(a20 + bb.x, a21 + bb.y);
        *(float2*)(o + 3 * DDIM) = make_float2(a30 + bb.x, a31 + bb.y);
    }

    // ================ PHASE 3: topk reduce + combine + gather ==============
    {
        const int row = blk;

        // wait for all 16 role-A blocks of this row's 32-row tile
        if (t == 0) waitcnt(&g_cnt2[row >> 5], tgt2);
        __syncthreads();

        if (warp < 2) {
            const int side = warp;
            unsigned long long c = g_cand[side][row][lane];
#pragma unroll
            for (int n = 0; n < TK; n++) {
                unsigned long long m = c;
#pragma unroll
                for (int off = 16; off >= 1; off >>= 1) {
                    unsigned long long o = __shfl_xor_sync(0xffffffffu, m, off);
                    if (o > m) m = o;
                }
                if (lane == 0) u.p3.s_top[side][n] = m;
                if (c == m) c = 0ull;
            }
        }
        __syncthreads();

        if (warp == 2) {
            unsigned long long c = 0ull;
            if (lane < 16) {
                const unsigned long long r4 = u.p3.s_top[0][lane >> 2];
                const unsigned long long c4 = u.p3.s_top[1][lane & 3];
                const float sum = unpackval(r4) + unpackval(c4);
                const int flat  = unpackidx(r4) * NK + unpackidx(c4);
                c = packcand(sum, flat);
            }
#pragma unroll
            for (int n = 0; n < TK; n++) {
                unsigned long long m = c;
#pragma unroll
                for (int off = 16; off >= 1; off >>= 1) {
                    unsigned long long o = __shfl_xor_sync(0xffffffffu, m, off);
                    if (o > m) m = o;
                }
                if (lane == 0) {
                    out[SC_OFF  + row * TK + n] = unpackval(m);
                    const int fi = unpackidx(m);
                    out[IDX_OFF + row * TK + n] = (float)fi;
                    u.p3.s_idx[n] = fi;
                }
                if (c == m) c = 0ull;
            }
        }
        __syncthreads();

        // gather 4 concept rows (4 x 192 float4), 3 per thread
#pragma unroll
        for (int k = 0; k < 3; k++) {
            const int i = t + k * 256;
            const int n = i / 192, j = i % 192;
            const int cid = u.p3.s_idx[n];
            const float4 val = ((const float4*)concepts)[(size_t)cid * 192 + j];
            ((float4*)(out + OC_OFF))[(size_t)(row * TK + n) * 192 + j] = val;
        }
    }
}

extern "C" void kernel_launch(void* const* d_in, const int* in_sizes, int n_in,
                              void* d_out, int out_size) {
    const float* regs     = (const float*)d_in[0];
    const float* row_keys = (const float*)d_in[1];
    const float* col_keys = (const float*)d_in[2];
    const float* concepts = (const float*)d_in[3];
    const float* gamma    = (const float*)d_in[4];
    const float* beta     = (const float*)d_in[5];
    const float* Wq       = (const float*)d_in[6];
    const float* bq       = (const float*)d_in[7];
    const float* Wqc      = (const float*)d_in[8];
    const float* bqc      = (const float*)d_in[9];
    float* out = (float*)d_out;

    fused_all<<<NBLK, 256>>>(regs, row_keys, col_keys, concepts, gamma, beta,
                             Wq, bq, Wqc, bqc, out);
}